// round 4
// baseline (speedup 1.0000x reference)
#include <cuda_runtime.h>
#include <cuda_fp16.h>
#include <cstdint>

#define DEV_INLINE __device__ __forceinline__

// ---------------- problem sizes ----------------
static constexpr int kB = 16384;
static constexpr int kD = 1024;
static constexpr int kU = 128;

// ---------------- tiling ----------------
static constexpr int DC    = 32;            // K per chunk
static constexpr int NCH   = kD / DC;       // 32 chunks
static constexpr int PAIRS = 3;             // stream pairs (0,1),(2,3),(4,5)
static constexpr int PAIR_BYTES = 128 * 128;      // 128 rows x 128B (two 64B stream halves)
static constexpr int HALF_BUF   = PAIRS * PAIR_BYTES;      // 49152: A region or B region
static constexpr int BUF_BYTES  = 2 * HALF_BUF;            // 98304 per buffer
static constexpr int SMEM_TOTAL = 2 * BUF_BYTES;           // 196608 (double buffered)

static constexpr int W_HALVES = NCH * PAIRS * 8192;        // 786432 fp16

// prepacked, SW128-swizzled fp16 weights: [chunk32][pair][128 rows][128B(two streams)]
__device__ __half g_Wpack[W_HALVES];

// ---------------- PTX helpers ----------------
DEV_INLINE uint32_t smem_u32(const void* p) {
    uint32_t a;
    asm("{ .reg .u64 t; cvta.to.shared.u64 t, %1; cvt.u32.u64 %0, t; }" : "=r"(a) : "l"(p));
    return a;
}

#define LDSM_X4(r, addr)                                                        \
    asm volatile("ldmatrix.sync.aligned.m8n8.x4.shared.b16 {%0,%1,%2,%3}, [%4];"\
                 : "=r"((r)[0]), "=r"((r)[1]), "=r"((r)[2]), "=r"((r)[3])       \
                 : "r"(addr))

DEV_INLINE void mma16816(float* d, const uint32_t* a, uint32_t b0, uint32_t b1) {
    asm volatile(
        "mma.sync.aligned.m16n8k16.row.col.f32.f16.f16.f32 "
        "{%0,%1,%2,%3}, {%4,%5,%6,%7}, {%8,%9}, {%0,%1,%2,%3};"
        : "+f"(d[0]), "+f"(d[1]), "+f"(d[2]), "+f"(d[3])
        : "r"(a[0]), "r"(a[1]), "r"(a[2]), "r"(a[3]), "r"(b0), "r"(b1));
}

// ---------------- weight prep: fp32 -> fp16, pair-interleaved + SW128 ----------------
__global__ void kan_prep_weights(const float* __restrict__ bw,
                                 const float* __restrict__ sw) {
    int idx = blockIdx.x * blockDim.x + threadIdx.x;
    if (idx >= W_HALVES) return;
    int hw  = idx & 63;            // half within 128B row
    int slo = hw >> 5;             // stream half (0/1)
    int k   = hw & 31;             // K within chunk
    int n   = (idx >> 6) & 127;    // output unit (B row)
    int t3  = idx >> 13;           // c2*3 + p
    int p   = t3 % 3;
    int c2  = t3 / 3;
    int s   = p * 2 + slo;         // stream 0..5
    int i   = c2 * DC + k;         // feature index
    float v = (s == 0) ? bw[i * kU + n]
                       : sw[(size_t)(i * kU + n) * 8 + (s - 1)];
    unsigned off = (unsigned)(n * 128 + slo * 64 + k * 2);
    unsigned swz = off ^ ((off >> 3) & 0x70);
    g_Wpack[(size_t)t3 * 8192 + (swz >> 1)] = __float2half(v);
}

// ---------------- main fused kernel ----------------
__global__ void __launch_bounds__(256, 1)
kan_main_kernel(const float* __restrict__ x, float* __restrict__ out) {
    extern __shared__ char smem[];
    const uint32_t smem_base = smem_u32(smem);
    const int tid  = threadIdx.x;
    const int wid  = tid >> 5;
    const int lane = tid & 31;

    // warp grid 2x4: warp tile 64x32
    const int mi = wid & 1;        // 0..1 -> rows mi*64
    const int ni = wid >> 1;       // 0..3 -> cols ni*32

    const int row_base = blockIdx.x * 128;

    // accumulators: [mb 0..3][nb 0..3][4], base (acc0) and spline (acc1)
    float acc0[4][4][4], acc1[4][4][4];
    #pragma unroll
    for (int a = 0; a < 4; ++a)
        #pragma unroll
        for (int b = 0; b < 4; ++b)
            #pragma unroll
            for (int j = 0; j < 4; ++j) { acc0[a][b][j] = 0.f; acc1[a][b][j] = 0.f; }

    // ---- ldmatrix lane addressing ----
    const int aRowLocal  = (lane & 7) + ((lane >> 3) & 1) * 8;
    const uint32_t kbAhi = ((lane >> 4) & 1) * 16;
    uint32_t aOff[4], aXor[4];
    #pragma unroll
    for (int mb = 0; mb < 4; ++mb) {
        int r = mi * 64 + mb * 16 + aRowLocal;
        aOff[mb] = (uint32_t)(r * 128);
        aXor[mb] = (uint32_t)((r & 7) << 4);
    }
    const int rB = ni * 32 + lane;
    const uint32_t bOff = (uint32_t)(rB * 128);
    const uint32_t bXor = (uint32_t)((rB & 7) << 4);

    // ---- producer mapping: thread -> row r = tid&127, col-half hf ----
    const int pr = tid & 127;
    const int hf = tid >> 7;                 // 0/1 -> cols hf*16..+15
    const float* xrow = x + (size_t)(row_base + pr) * kD + hf * 16;

    const float C5   = 6.737946999085467e-3f;  // exp(-5)
    const float C125 = 0.2865047968601901f;    // exp(-1.25)

    // producer lambda-ish: compute + store A streams for chunk c into buffer buf
    // (written inline twice: prologue and steady-state)
    auto produceA = [&](int c, uint32_t abase, const float4* xq) {
        union { __half2 h2[8]; uint4 u4[2]; } st[6];
        #pragma unroll
        for (int j = 0; j < 4; ++j) {
            float xs[4] = {xq[j].x, xq[j].y, xq[j].z, xq[j].w};
            float r0[4], r1[4], r2[4], r3[4], r4[4];
            #pragma unroll
            for (int e = 0; e < 4; ++e) {
                float xv = xs[e];
                float s = __expf(-5.f * xv * xv);
                float t = __expf(5.f * xv);
                float u = __expf(-5.f * xv);
                r0[e] = s * u * u * C5;   // c=-1
                r1[e] = s * u * C125;     // c=-0.5
                r2[e] = s;                // c=0
                r3[e] = s * t * C125;     // c=0.5
                r4[e] = s * t * t * C5;   // c=1
            }
            st[0].h2[j * 2]     = __floats2half2_rn(xs[0], xs[1]);
            st[0].h2[j * 2 + 1] = __floats2half2_rn(xs[2], xs[3]);
            st[1].h2[j * 2]     = __floats2half2_rn(r0[0], r0[1]);
            st[1].h2[j * 2 + 1] = __floats2half2_rn(r0[2], r0[3]);
            st[2].h2[j * 2]     = __floats2half2_rn(r1[0], r1[1]);
            st[2].h2[j * 2 + 1] = __floats2half2_rn(r1[2], r1[3]);
            st[3].h2[j * 2]     = __floats2half2_rn(r2[0], r2[1]);
            st[3].h2[j * 2 + 1] = __floats2half2_rn(r2[2], r2[3]);
            st[4].h2[j * 2]     = __floats2half2_rn(r3[0], r3[1]);
            st[4].h2[j * 2 + 1] = __floats2half2_rn(r3[2], r3[3]);
            st[5].h2[j * 2]     = __floats2half2_rn(r4[0], r4[1]);
            st[5].h2[j * 2 + 1] = __floats2half2_rn(r4[2], r4[3]);
        }
        #pragma unroll
        for (int s = 0; s < 6; ++s) {
            int p = s >> 1, slo = s & 1;
            #pragma unroll
            for (int jj = 0; jj < 2; ++jj) {
                unsigned off = (unsigned)(pr * 128 + slo * 64 + hf * 32 + jj * 16);
                unsigned swz = off ^ ((off >> 3) & 0x70);
                *reinterpret_cast<uint4*>(smem + abase - smem_base + p * PAIR_BYTES + swz) =
                    st[s].u4[jj];
            }
        }
        (void)c;
    };

    // -------- prologue: produce chunk 0 into buffer 0 --------
    {
        float4 xq[4];
        #pragma unroll
        for (int j = 0; j < 4; ++j)
            xq[j] = *reinterpret_cast<const float4*>(xrow + 0 * DC + j * 4);
        // W copy chunk 0
        const uint4* wsrc = reinterpret_cast<const uint4*>(g_Wpack);
        uint4* wdst = reinterpret_cast<uint4*>(smem + HALF_BUF);
        #pragma unroll
        for (int j = 0; j < 12; ++j) wdst[tid + j * 256] = wsrc[tid + j * 256];
        produceA(0, smem_base, xq);
    }
    __syncthreads();

    // -------- main loop --------
    for (int c = 0; c < NCH; ++c) {
        const uint32_t bufc = smem_base + (uint32_t)((c & 1) * BUF_BYTES);
        const uint32_t bufn = smem_base + (uint32_t)(((c + 1) & 1) * BUF_BYTES);

        // prefetch next chunk inputs into registers (latency hidden by consume)
        float4 xq[4];
        uint4  wq[12];
        if (c + 1 < NCH) {
            #pragma unroll
            for (int j = 0; j < 4; ++j)
                xq[j] = *reinterpret_cast<const float4*>(xrow + (c + 1) * DC + j * 4);
            const uint4* wsrc = reinterpret_cast<const uint4*>(g_Wpack) +
                                (size_t)(c + 1) * (PAIRS * 8192 / 8);
            #pragma unroll
            for (int j = 0; j < 12; ++j) wq[j] = wsrc[tid + j * 256];
        }

        // ---- consume chunk c ----
        const uint32_t aBase = bufc;
        const uint32_t bBase = bufc + HALF_BUF;
        #pragma unroll
        for (int q = 0; q < 2; ++q) {
            #pragma unroll
            for (int s = 0; s < 6; ++s) {
                const int p = s >> 1, slo = s & 1;
                const uint32_t pOff = (uint32_t)(p * PAIR_BYTES);
                const uint32_t kbA  = (uint32_t)(slo * 64 + q * 32) + kbAhi;

                uint32_t a[16];
                #pragma unroll
                for (int mb = 0; mb < 4; ++mb) {
                    uint32_t addr = aBase + pOff + aOff[mb] + (kbA ^ aXor[mb]);
                    LDSM_X4(a + mb * 4, addr);
                }
                uint32_t bb[8];
                #pragma unroll
                for (int h = 0; h < 2; ++h) {
                    uint32_t kb = (uint32_t)(slo * 64 + q * 32 + h * 16);
                    uint32_t addr = bBase + pOff + bOff + (kb ^ bXor);
                    LDSM_X4(bb + h * 4, addr);
                }

                if (s == 0) {
                    #pragma unroll
                    for (int mb = 0; mb < 4; ++mb)
                        #pragma unroll
                        for (int nb = 0; nb < 4; ++nb)
                            mma16816(acc0[mb][nb], a + mb * 4, bb[nb], bb[4 + nb]);
                } else {
                    #pragma unroll
                    for (int mb = 0; mb < 4; ++mb)
                        #pragma unroll
                        for (int nb = 0; nb < 4; ++nb)
                            mma16816(acc1[mb][nb], a + mb * 4, bb[nb], bb[4 + nb]);
                }
            }
        }

        // ---- produce chunk c+1 into the other buffer ----
        if (c + 1 < NCH) {
            uint4* wdst = reinterpret_cast<uint4*>(smem + (bufn - smem_base) + HALF_BUF);
            #pragma unroll
            for (int j = 0; j < 12; ++j) wdst[tid + j * 256] = wq[j];
            produceA(c + 1, bufn, xq);
        }
        __syncthreads();
    }

    // -------- epilogue: SiLU(base) + spline --------
    {
        const int colBase = ni * 32 + (lane & 3) * 2;
        #pragma unroll
        for (int mb = 0; mb < 4; ++mb) {
            int row0 = row_base + mi * 64 + mb * 16 + (lane >> 2);
            #pragma unroll
            for (int nb = 0; nb < 4; ++nb) {
                int col = colBase + nb * 8;
                float z0 = acc0[mb][nb][0], z1 = acc0[mb][nb][1];
                float z2 = acc0[mb][nb][2], z3 = acc0[mb][nb][3];
                float2 v0, v1;
                v0.x = __fdividef(z0, 1.f + __expf(-z0)) + acc1[mb][nb][0];
                v0.y = __fdividef(z1, 1.f + __expf(-z1)) + acc1[mb][nb][1];
                v1.x = __fdividef(z2, 1.f + __expf(-z2)) + acc1[mb][nb][2];
                v1.y = __fdividef(z3, 1.f + __expf(-z3)) + acc1[mb][nb][3];
                *reinterpret_cast<float2*>(out + (size_t)row0 * kU + col)       = v0;
                *reinterpret_cast<float2*>(out + (size_t)(row0 + 8) * kU + col) = v1;
            }
        }
    }
}

// ---------------- launch ----------------
extern "C" void kernel_launch(void* const* d_in, const int* in_sizes, int n_in,
                              void* d_out, int out_size) {
    (void)in_sizes; (void)n_in; (void)out_size;
    const float* x  = (const float*)d_in[0];
    const float* bw = (const float*)d_in[1];
    const float* sw = (const float*)d_in[2];
    float* out = (float*)d_out;

    cudaFuncSetAttribute(kan_main_kernel,
                         cudaFuncAttributeMaxDynamicSharedMemorySize, SMEM_TOTAL);

    kan_prep_weights<<<(W_HALVES + 255) / 256, 256>>>(bw, sw);
    kan_main_kernel<<<kB / 128, 256, SMEM_TOTAL>>>(x, out);
}

// round 5
// speedup vs baseline: 1.2408x; 1.2408x over previous
#include <cuda_runtime.h>
#include <cuda_fp16.h>
#include <cstdint>

#define DEV_INLINE __device__ __forceinline__

// ---------------- problem sizes ----------------
static constexpr int kB = 16384;
static constexpr int kD = 1024;
static constexpr int kU = 128;

// ---------------- tiling ----------------
static constexpr int DC    = 32;            // K per chunk
static constexpr int NCH   = kD / DC;       // 32 chunks
static constexpr int PAIRS = 3;             // stream pairs (0,1),(2,3),(4,5)
static constexpr int PAIR_BYTES = 128 * 128;           // 128 rows x 128B
static constexpr int HALF_BUF   = PAIRS * PAIR_BYTES;  // 49152 (A region or B region)
static constexpr int BUF_BYTES  = 2 * HALF_BUF;        // 98304 per buffer
static constexpr int SMEM_TOTAL = 2 * BUF_BYTES;       // 196608 double-buffered

static constexpr int W_HALVES = NCH * PAIRS * 8192;    // 786432 fp16
static constexpr int W_U4_PER_CHUNK = PAIRS * 8192 * 2 / 16;  // 3072 uint4

static constexpr int NTHREADS = 384;        // 8 consumer warps + 4 producer warps

// prepacked, SW128-swizzled fp16 weights: [chunk32][pair][128 rows][128B (2 streams)]
__device__ __half g_Wpack[W_HALVES];

// ---------------- PTX helpers ----------------
DEV_INLINE uint32_t smem_u32(const void* p) {
    uint32_t a;
    asm("{ .reg .u64 t; cvta.to.shared.u64 t, %1; cvt.u32.u64 %0, t; }" : "=r"(a) : "l"(p));
    return a;
}

#define LDSM_X4(r, addr)                                                        \
    asm volatile("ldmatrix.sync.aligned.m8n8.x4.shared.b16 {%0,%1,%2,%3}, [%4];"\
                 : "=r"((r)[0]), "=r"((r)[1]), "=r"((r)[2]), "=r"((r)[3])       \
                 : "r"(addr))

DEV_INLINE void mma16816(float* d, const uint32_t* a, uint32_t b0, uint32_t b1) {
    asm volatile(
        "mma.sync.aligned.m16n8k16.row.col.f32.f16.f16.f32 "
        "{%0,%1,%2,%3}, {%4,%5,%6,%7}, {%8,%9}, {%0,%1,%2,%3};"
        : "+f"(d[0]), "+f"(d[1]), "+f"(d[2]), "+f"(d[3])
        : "r"(a[0]), "r"(a[1]), "r"(a[2]), "r"(a[3]), "r"(b0), "r"(b1));
}

DEV_INLINE void cp_async16(uint32_t smem_dst, const void* gsrc) {
    asm volatile("cp.async.cg.shared.global [%0], [%1], 16;"
                 :: "r"(smem_dst), "l"(gsrc) : "memory");
}
DEV_INLINE void cp_async_commit() { asm volatile("cp.async.commit_group;" ::: "memory"); }
DEV_INLINE void cp_async_wait_all() { asm volatile("cp.async.wait_group 0;" ::: "memory"); }

// ---------------- weight prep: fp32 -> fp16, pair-interleaved + SW128 ----------------
__global__ void kan_prep_weights(const float* __restrict__ bw,
                                 const float* __restrict__ sw) {
    int idx = blockIdx.x * blockDim.x + threadIdx.x;
    if (idx >= W_HALVES) return;
    int hw  = idx & 63;            // half within 128B row
    int slo = hw >> 5;             // stream half (0/1)
    int k   = hw & 31;             // K within chunk
    int n   = (idx >> 6) & 127;    // output unit (B row)
    int t3  = idx >> 13;           // c*3 + p
    int p   = t3 % 3;
    int c   = t3 / 3;
    int s   = p * 2 + slo;         // stream 0..5
    int i   = c * DC + k;          // feature index
    float v = (s == 0) ? bw[i * kU + n]
                       : sw[(size_t)(i * kU + n) * 8 + (s - 1)];
    unsigned off = (unsigned)(n * 128 + slo * 64 + k * 2);
    unsigned swz = off ^ ((off >> 3) & 0x70);
    g_Wpack[(size_t)t3 * 8192 + (swz >> 1)] = __float2half(v);
}

// ---------------- main fused kernel (warp-specialized) ----------------
__global__ void __launch_bounds__(NTHREADS, 1)
kan_main_kernel(const float* __restrict__ x, float* __restrict__ out) {
    extern __shared__ char smem[];
    const uint32_t smem_base = smem_u32(smem);
    const int tid  = threadIdx.x;
    const int wid  = tid >> 5;
    const int lane = tid & 31;
    const int row_base = blockIdx.x * 128;

    // rbf chain constants
    const float E375p = 42.52108200006278f;    // e^{3.75}
    const float E125p = 3.4903429574597902f;   // e^{1.25}
    const float E125m = 0.2865047968601901f;   // e^{-1.25}
    const float E375m = 0.023517745856009107f; // e^{-3.75}

    if (wid >= 8) {
        // ================= PRODUCER warps (4 warps, 128 threads) =================
        const int pr = tid - 256;                       // row 0..127
        const float* xp = x + (size_t)(row_base + pr) * kD;
        const uint32_t aSw = (uint32_t)((pr & 7) << 4); // SW128 xor for this row

        // produce chunk `c` into buffer at aRegion (A) given 8 prefetched float4
        auto produce = [&](uint32_t aRegion, const float4* xq) {
            #pragma unroll
            for (int g = 0; g < 4; ++g) {               // col groups of 8
                float xs[8];
                xs[0]=xq[2*g].x; xs[1]=xq[2*g].y; xs[2]=xq[2*g].z; xs[3]=xq[2*g].w;
                xs[4]=xq[2*g+1].x; xs[5]=xq[2*g+1].y; xs[6]=xq[2*g+1].z; xs[7]=xq[2*g+1].w;
                union { __half2 h2[4]; uint4 u4; } st[6];
                #pragma unroll
                for (int e = 0; e < 8; e += 2) {
                    float a0 = xs[e] + 1.f, a1 = xs[e+1] + 1.f;
                    float y0a = __expf(-5.f * a0 * a0);
                    float y0b = __expf(-5.f * a1 * a1);
                    float ta  = __expf(5.f * xs[e]);
                    float tb  = __expf(5.f * xs[e+1]);
                    float y1a = y0a * ta * E375p, y1b = y0b * tb * E375p;
                    float y2a = y1a * ta * E125p, y2b = y1b * tb * E125p;
                    float y3a = y2a * ta * E125m, y3b = y2b * tb * E125m;
                    float y4a = y3a * ta * E375m, y4b = y3b * tb * E375m;
                    int j = e >> 1;
                    st[0].h2[j] = __floats2half2_rn(xs[e], xs[e+1]);
                    st[1].h2[j] = __floats2half2_rn(y0a, y0b);
                    st[2].h2[j] = __floats2half2_rn(y1a, y1b);
                    st[3].h2[j] = __floats2half2_rn(y2a, y2b);
                    st[4].h2[j] = __floats2half2_rn(y3a, y3b);
                    st[5].h2[j] = __floats2half2_rn(y4a, y4b);
                }
                #pragma unroll
                for (int s = 0; s < 6; ++s) {
                    int p = s >> 1, slo = s & 1;
                    unsigned off = (unsigned)(pr * 128 + slo * 64 + g * 16);
                    unsigned swz = off ^ aSw;
                    *reinterpret_cast<uint4*>(smem + (aRegion - smem_base) +
                                              p * PAIR_BYTES + swz) = st[s].u4;
                }
            }
        };

        auto copyW = [&](int c, uint32_t bRegion) {
            const char* src = reinterpret_cast<const char*>(g_Wpack) +
                              (size_t)c * (PAIRS * 8192 * 2);
            // 3072 uint4 over 128 producer threads -> 24 each
            #pragma unroll
            for (int j = 0; j < W_U4_PER_CHUNK / 128; ++j) {
                int i = pr + j * 128;
                cp_async16(bRegion + i * 16, src + i * 16);
            }
            cp_async_commit();
        };

        // prologue: chunk 0 -> buffer 0
        {
            float4 xq[8];
            #pragma unroll
            for (int j = 0; j < 8; ++j)
                xq[j] = *reinterpret_cast<const float4*>(xp + 0 * DC + j * 4);
            copyW(0, smem_base + HALF_BUF);
            produce(smem_base, xq);
            cp_async_wait_all();
        }
        __syncthreads();

        for (int c = 0; c < NCH; ++c) {
            if (c + 1 < NCH) {
                const uint32_t bufn = smem_base + (uint32_t)(((c + 1) & 1) * BUF_BYTES);
                float4 xq[8];
                #pragma unroll
                for (int j = 0; j < 8; ++j)
                    xq[j] = *reinterpret_cast<const float4*>(xp + (c + 1) * DC + j * 4);
                copyW(c + 1, bufn + HALF_BUF);
                produce(bufn, xq);
                cp_async_wait_all();
            }
            __syncthreads();
        }
        // producers done (no epilogue work)
    } else {
        // ================= CONSUMER warps (8 warps): 64x32 tiles =================
        const int mi = wid & 1;        // rows mi*64
        const int ni = wid >> 1;       // cols ni*32

        float acc0[4][4][4], acc1[4][4][4];
        #pragma unroll
        for (int a = 0; a < 4; ++a)
            #pragma unroll
            for (int b = 0; b < 4; ++b)
                #pragma unroll
                for (int j = 0; j < 4; ++j) { acc0[a][b][j] = 0.f; acc1[a][b][j] = 0.f; }

        const int aRowLocal  = (lane & 7) + ((lane >> 3) & 1) * 8;
        const uint32_t kbAhi = ((lane >> 4) & 1) * 16;
        uint32_t aOff[4];
        #pragma unroll
        for (int mb = 0; mb < 4; ++mb)
            aOff[mb] = (uint32_t)((mi * 64 + mb * 16 + aRowLocal) * 128);
        const int rB = ni * 32 + lane;
        const uint32_t bOff = (uint32_t)(rB * 128);
        const uint32_t bXor = (uint32_t)((rB & 7) << 4);

        __syncthreads();  // matches producer prologue sync

        for (int c = 0; c < NCH; ++c) {
            const uint32_t bufc  = smem_base + (uint32_t)((c & 1) * BUF_BYTES);
            const uint32_t aBase = bufc;
            const uint32_t bBase = bufc + HALF_BUF;

            #pragma unroll
            for (int kk = 0; kk < 2; ++kk) {
                #pragma unroll
                for (int s = 0; s < 6; ++s) {
                    const int p = s >> 1, slo = s & 1;
                    const uint32_t pOff = (uint32_t)(p * PAIR_BYTES);
                    const uint32_t kbA  = (uint32_t)(slo * 64 + kk * 32) + kbAhi;

                    uint32_t a[16];
                    #pragma unroll
                    for (int mb = 0; mb < 4; ++mb) {
                        uint32_t ax = (aOff[mb] >> 3) & 0x70;
                        uint32_t addr = aBase + pOff + aOff[mb] + (kbA ^ ax);
                        LDSM_X4(a + mb * 4, addr);
                    }
                    uint32_t bb[8];
                    #pragma unroll
                    for (int h = 0; h < 2; ++h) {
                        uint32_t kb = (uint32_t)(slo * 64 + kk * 32 + h * 16);
                        uint32_t addr = bBase + pOff + bOff + (kb ^ bXor);
                        LDSM_X4(bb + h * 4, addr);
                    }

                    if (s == 0) {
                        #pragma unroll
                        for (int mb = 0; mb < 4; ++mb)
                            #pragma unroll
                            for (int nb = 0; nb < 4; ++nb)
                                mma16816(acc0[mb][nb], a + mb * 4, bb[nb], bb[4 + nb]);
                    } else {
                        #pragma unroll
                        for (int mb = 0; mb < 4; ++mb)
                            #pragma unroll
                            for (int nb = 0; nb < 4; ++nb)
                                mma16816(acc1[mb][nb], a + mb * 4, bb[nb], bb[4 + nb]);
                    }
                }
            }
            __syncthreads();
        }

        // epilogue: SiLU(base) + spline
        const int colBase = ni * 32 + (lane & 3) * 2;
        #pragma unroll
        for (int mb = 0; mb < 4; ++mb) {
            int row0 = row_base + mi * 64 + mb * 16 + (lane >> 2);
            #pragma unroll
            for (int nb = 0; nb < 4; ++nb) {
                int col = colBase + nb * 8;
                float z0 = acc0[mb][nb][0], z1 = acc0[mb][nb][1];
                float z2 = acc0[mb][nb][2], z3 = acc0[mb][nb][3];
                float2 v0, v1;
                v0.x = __fdividef(z0, 1.f + __expf(-z0)) + acc1[mb][nb][0];
                v0.y = __fdividef(z1, 1.f + __expf(-z1)) + acc1[mb][nb][1];
                v1.x = __fdividef(z2, 1.f + __expf(-z2)) + acc1[mb][nb][2];
                v1.y = __fdividef(z3, 1.f + __expf(-z3)) + acc1[mb][nb][3];
                *reinterpret_cast<float2*>(out + (size_t)row0 * kU + col)       = v0;
                *reinterpret_cast<float2*>(out + (size_t)(row0 + 8) * kU + col) = v1;
            }
        }
    }
}

// ---------------- launch ----------------
extern "C" void kernel_launch(void* const* d_in, const int* in_sizes, int n_in,
                              void* d_out, int out_size) {
    (void)in_sizes; (void)n_in; (void)out_size;
    const float* x  = (const float*)d_in[0];
    const float* bw = (const float*)d_in[1];
    const float* sw = (const float*)d_in[2];
    float* out = (float*)d_out;

    cudaFuncSetAttribute(kan_main_kernel,
                         cudaFuncAttributeMaxDynamicSharedMemorySize, SMEM_TOTAL);

    kan_prep_weights<<<(W_HALVES + 255) / 256, 256>>>(bw, sw);
    kan_main_kernel<<<kB / 128, NTHREADS, SMEM_TOTAL>>>(x, out);
}